// round 1
// baseline (speedup 1.0000x reference)
#include <cuda_runtime.h>

#define TSEQ  1024
#define NB    512
#define RTASK 8          // sequences per block
#define NBLK  128        // 64 fwd + 64 bwd blocks

// final hidden states: [dir][batch][64]
__device__ float g_h[2 * NB * 64];

static __device__ __forceinline__ unsigned long long pk2(float lo, float hi) {
    unsigned long long r;
    asm("mov.b64 %0, {%1,%2};" : "=l"(r) : "f"(lo), "f"(hi));
    return r;
}
static __device__ __forceinline__ void upk2(unsigned long long v, float &lo, float &hi) {
    asm("mov.b64 {%0,%1}, %2;" : "=f"(lo), "=f"(hi) : "l"(v));
}
static __device__ __forceinline__ void ffma2(unsigned long long &d,
                                             unsigned long long a,
                                             unsigned long long b) {
    asm("fma.rn.f32x2 %0, %1, %2, %0;" : "+l"(d) : "l"(a), "l"(b));
}
static __device__ __forceinline__ float sigm(float x) {
    return 1.0f / (1.0f + __expf(-x));
}
static __device__ __forceinline__ float tanh_acc(float x) {
    // tanh(x) = 1 - 2/(exp(2x)+1); saturates correctly at +/-inf of expf
    float e = __expf(2.0f * x);
    return 1.0f - 2.0f / (e + 1.0f);
}

// Persistent bidirectional LSTM kernel.
// Grid: 128 blocks x 256 threads. Blocks [0,64): forward, [64,128): backward.
// Each block owns 8 sequences (one direction) and runs all 1024 steps.
// Thread j owns gate-column j (of 256) for all 8 sequences; the 128 [W;U]
// weights of that column live in 64 packed f32x2 registers. The f32x2 pair
// is packed along the reduction dim, so state pairs come straight out of
// LDS.128 broadcasts with no repacking.
extern "C" __global__ void __launch_bounds__(256, 1)
lstm_kernel(const void* __restrict__ xraw, const float* __restrict__ emb,
            const float* __restrict__ Wf, const float* __restrict__ Uf,
            const float* __restrict__ bf,
            const float* __restrict__ Wb, const float* __restrict__ Ub,
            const float* __restrict__ bb)
{
    __shared__ __align__(16) float s[RTASK][128];   // per task: [0..63]=x_t, [64..127]=h
    __shared__ float zs[RTASK][256];                // gate pre-activations
    __shared__ int   idxs[2][RTASK];                // token ids, ping-pong by step parity

    const int tid = threadIdx.x;
    const int dir = (blockIdx.x >= 64) ? 1 : 0;
    const int b0  = (blockIdx.x & 63) * RTASK;

    const int*       x32 = (const int*)xraw;
    const long long* x64 = (const long long*)xraw;
    // int64 tokens have zero high words (values < 2^31); detect element width.
    const bool is64 = ((x32[1] | x32[3] | x32[5] | x32[7]) == 0);

    const float* Wd = dir ? Wb : Wf;
    const float* Ud = dir ? Ub : Uf;
    const float* bd = dir ? bb : bf;

    // ---- load this column's weights into registers (packed pairs) ----
    unsigned long long wreg[64];
#pragma unroll
    for (int p = 0; p < 32; p++)
        wreg[p] = pk2(Wd[(2 * p) * 256 + tid], Wd[(2 * p + 1) * 256 + tid]);
#pragma unroll
    for (int p = 32; p < 64; p++)
        wreg[p] = pk2(Ud[(2 * p - 64) * 256 + tid], Ud[(2 * p - 63) * 256 + tid]);
    const float bj = bd[tid];

    const int u  = tid & 63;        // hidden unit for stage C
    const int rp = tid >> 6;        // 0..3 -> task pair (2rp, 2rp+1)
    const int rA = tid >> 6;        // emb fill: tasks 0..3
    const int rB = 4 + (tid >> 6);  // emb fill: tasks 4..7
    const int kk = tid & 63;

    // ---- prologue: token ids for step 0 and 1, emb for step 0, h=0 ----
    if (tid < RTASK) {
        const long long base = (long long)(b0 + tid) * TSEQ;
        const int t0 = dir ? (TSEQ - 1) : 0;
        const int t1 = dir ? (TSEQ - 2) : 1;
        idxs[0][tid] = is64 ? (int)x64[base + t0] : x32[base + t0];
        idxs[1][tid] = is64 ? (int)x64[base + t1] : x32[base + t1];
    }
    __syncthreads();
    {
        const int ra = idxs[0][rA], rb = idxs[0][rB];
        s[rA][kk]      = emb[(long long)ra * 64 + kk];
        s[rB][kk]      = emb[(long long)rb * 64 + kk];
        s[rA][64 + kk] = 0.f;
        s[rB][64 + kk] = 0.f;
    }
    float hreg[2] = {0.f, 0.f};
    float creg[2] = {0.f, 0.f};
    __syncthreads();

    for (int t = 0; t < TSEQ; t++) {
        const int pcur = t & 1, pnxt = pcur ^ 1;

        // ================= stage B: z = [x;h] @ [W;U] + b =================
        // grab this step's masks before C overwrites the slot at t+... (bar-ordered)
        const int m0 = idxs[pcur][2 * rp];
        const int m1 = idxs[pcur][2 * rp + 1];

        // prefetch next step's embedding rows (latency hidden under the GEMM)
        float e0 = 0.f, e1 = 0.f;
        const int have_e = (t + 1 < TSEQ);
        if (have_e) {
            const int ra = idxs[pnxt][rA], rb = idxs[pnxt][rB];
            e0 = emb[(long long)ra * 64 + kk];
            e1 = emb[(long long)rb * 64 + kk];
        }
        long long nidx = 0;
        const int have_i = (tid < RTASK) && (t + 2 < TSEQ);
        if (have_i) {
            const int tn = dir ? (TSEQ - 1 - (t + 2)) : (t + 2);
            const long long base = (long long)(b0 + tid) * TSEQ;
            nidx = is64 ? x64[base + tn] : (long long)x32[base + tn];
        }

#pragma unroll 1
        for (int r = 0; r < RTASK; r++) {
            const ulonglong2* srow = (const ulonglong2*)(&s[r][0]);
            unsigned long long a0 = 0ull, a1 = 0ull;   // two chains for ILP
#pragma unroll
            for (int q = 0; q < 16; q++) {
                const ulonglong2 v0 = srow[2 * q];
                const ulonglong2 v1 = srow[2 * q + 1];
                ffma2(a0, v0.x, wreg[4 * q + 0]);
                ffma2(a1, v0.y, wreg[4 * q + 1]);
                ffma2(a0, v1.x, wreg[4 * q + 2]);
                ffma2(a1, v1.y, wreg[4 * q + 3]);
            }
            float p0, p1, q0, q1;
            upk2(a0, p0, p1);
            upk2(a1, q0, q1);
            zs[r][tid] = bj + ((p0 + q0) + (p1 + q1));
        }
        __syncthreads();

        // ================= stage C: gates, state update, prefetch commit ====
#pragma unroll
        for (int c = 0; c < 2; c++) {
            const int r = 2 * rp + c;
            const float zi = zs[r][u];
            const float zf = zs[r][64 + u];
            const float zg = zs[r][128 + u];
            const float zo = zs[r][192 + u];
            const float ig = sigm(zi);
            const float fg = sigm(zf);
            const float gg = tanh_acc(zg);
            const float og = sigm(zo);
            const float cn = fg * creg[c] + ig * gg;
            const float hn = og * tanh_acc(cn);
            const int m = c ? m1 : m0;
            if (m != 0) { creg[c] = cn; hreg[c] = hn; }
            s[r][64 + u] = hreg[c];          // h for next step (old value if masked)
        }
        if (have_e) { s[rA][kk] = e0; s[rB][kk] = e1; }
        if (have_i) idxs[pcur][tid] = (int)nidx;   // becomes idx[t+2]
        __syncthreads();
    }

    // ---- write final hidden states ----
#pragma unroll
    for (int c = 0; c < 2; c++) {
        const int r = 2 * rp + c;
        g_h[(dir * NB + (b0 + r)) * 64 + u] = hreg[c];
    }
}

// Tiny head: out[b] = relu(concat(hf,hb) @ W1 + b1) @ W2 + b2
extern "C" __global__ void head_kernel(const float* __restrict__ W1,
                                       const float* __restrict__ b1,
                                       const float* __restrict__ W2,
                                       const float* __restrict__ b2,
                                       float* __restrict__ out)
{
    const int b = blockIdx.x;
    const int u = threadIdx.x;  // 32 hidden units
    const float* hf = &g_h[b * 64];
    const float* hb = &g_h[(NB + b) * 64];
    float acc = b1[u];
#pragma unroll
    for (int k = 0; k < 64; k++) acc = fmaf(hf[k], W1[k * 32 + u], acc);
#pragma unroll
    for (int k = 0; k < 64; k++) acc = fmaf(hb[k], W1[(64 + k) * 32 + u], acc);
    float v = fmaxf(acc, 0.f) * W2[u];
#pragma unroll
    for (int off = 16; off > 0; off >>= 1)
        v += __shfl_xor_sync(0xffffffffu, v, off);
    if (u == 0) out[b] = v + b2[0];
}

extern "C" void kernel_launch(void* const* d_in, const int* in_sizes, int n_in,
                              void* d_out, int out_size)
{
    const void*  x   = d_in[0];
    const float* emb = (const float*)d_in[1];
    const float* Wf  = (const float*)d_in[2];
    const float* Uf  = (const float*)d_in[3];
    const float* bf  = (const float*)d_in[4];
    const float* Wb  = (const float*)d_in[5];
    const float* Ub  = (const float*)d_in[6];
    const float* bb  = (const float*)d_in[7];
    const float* W1  = (const float*)d_in[8];
    const float* b1  = (const float*)d_in[9];
    const float* W2  = (const float*)d_in[10];
    const float* b2  = (const float*)d_in[11];

    lstm_kernel<<<NBLK, 256>>>(x, emb, Wf, Uf, bf, Wb, Ub, bb);
    head_kernel<<<NB, 32>>>(W1, b1, W2, b2, (float*)d_out);
}

// round 2
// speedup vs baseline: 1.0634x; 1.0634x over previous
#include <cuda_runtime.h>

#define TSEQ    1024
#define NB      512
#define RTASK   8
#define NBLK    128
#define VOCABP1 50001

// Precomputed zx table: zw[dir][token][gate] = emb[token] @ W_dir + b_dir  (~102.4 MB)
__device__ float g_zw[2][VOCABP1][256];
// final hidden states: [dir][batch][64]
__device__ float g_h[2 * NB * 64];

static __device__ __forceinline__ unsigned long long pk2(float lo, float hi) {
    unsigned long long r;
    asm("mov.b64 %0, {%1,%2};" : "=l"(r) : "f"(lo), "f"(hi));
    return r;
}
static __device__ __forceinline__ void upk2(unsigned long long v, float &lo, float &hi) {
    asm("mov.b64 {%0,%1}, %2;" : "=f"(lo), "=f"(hi) : "l"(v));
}
static __device__ __forceinline__ void ffma2(unsigned long long &d,
                                             unsigned long long a,
                                             unsigned long long b) {
    asm("fma.rn.f32x2 %0, %1, %2, %0;" : "+l"(d) : "l"(a), "l"(b));
}
static __device__ __forceinline__ float sigm(float x) {
    return 1.0f / (1.0f + __expf(-x));
}
static __device__ __forceinline__ float tanh_acc(float x) {
    float e = __expf(2.0f * x);
    return 1.0f - 2.0f / (e + 1.0f);
}

// ============================================================================
// Phase 1: zw[dir][v][j] = sum_k emb[v][k] * W_dir[k][j] + b_dir[j]
// Fully parallel over vocab; ~1.6 G MAC. Grid (782, 2), 256 threads.
// ============================================================================
extern "C" __global__ void __launch_bounds__(256)
zw_kernel(const float* __restrict__ emb,
          const float* __restrict__ Wf, const float* __restrict__ bf,
          const float* __restrict__ Wb, const float* __restrict__ bb)
{
    __shared__ __align__(16) float ebuf[64][64];
    const int dir  = blockIdx.y;
    const int base = blockIdx.x * 64;
    const int j    = threadIdx.x;
    const float* W  = dir ? Wb : Wf;
    const float* bv = dir ? bb : bf;

    unsigned long long wreg[32];
#pragma unroll
    for (int p = 0; p < 32; p++)
        wreg[p] = pk2(W[(2 * p) * 256 + j], W[(2 * p + 1) * 256 + j]);
    const float bj = bv[j];

#pragma unroll
    for (int i = 0; i < 16; i++) {
        const int lin = i * 256 + j;
        const int r = lin >> 6, c = lin & 63;
        const int row = base + r;
        ebuf[r][c] = (row < VOCABP1) ? emb[(long long)row * 64 + c] : 0.f;
    }
    __syncthreads();

    float* outp = &g_zw[dir][0][0];
#pragma unroll 1
    for (int r = 0; r < 64; r++) {
        if (base + r >= VOCABP1) break;
        const ulonglong2* srow = (const ulonglong2*)(&ebuf[r][0]);
        unsigned long long a0 = 0ull, a1 = 0ull;
#pragma unroll
        for (int q = 0; q < 8; q++) {
            const ulonglong2 v0 = srow[2 * q];
            const ulonglong2 v1 = srow[2 * q + 1];
            ffma2(a0, v0.x, wreg[4 * q + 0]);
            ffma2(a1, v0.y, wreg[4 * q + 1]);
            ffma2(a0, v1.x, wreg[4 * q + 2]);
            ffma2(a1, v1.y, wreg[4 * q + 3]);
        }
        float p0, p1, q0, q1;
        upk2(a0, p0, p1);
        upk2(a1, q0, q1);
        outp[(long long)(base + r) * 256 + j] = bj + ((p0 + q0) + (p1 + q1));
    }
}

// ============================================================================
// Phase 2: recurrent h@U + gates. 128 blocks x 512 threads (16 warps).
// Thread (col = tid>>1, khalf = tid&1): 16 packed U pairs in registers,
// partial dot combined via shfl_xor(1). zx rows prefetched 1 step ahead.
// ============================================================================
extern "C" __global__ void __launch_bounds__(512, 1)
lstm_kernel(const void* __restrict__ xraw,
            const float* __restrict__ Uf, const float* __restrict__ Ub)
{
    __shared__ __align__(16) float hs[RTASK][64];        // hidden state
    __shared__ float zs[RTASK][256];                     // gate pre-activations
    __shared__ __align__(16) float zxs[2][RTASK][256];   // zx double buffer
    __shared__ int   idxs[2][RTASK];                     // token ids, ping-pong

    const int tid = threadIdx.x;
    const int dir = (blockIdx.x >= 64) ? 1 : 0;
    const int b0  = (blockIdx.x & 63) * RTASK;

    const int*       x32 = (const int*)xraw;
    const long long* x64 = (const long long*)xraw;
    const bool is64 = ((x32[1] | x32[3] | x32[5] | x32[7]) == 0);

    const float* U   = dir ? Ub : Uf;
    const float* zwd = &g_zw[dir][0][0];

    const int col = tid >> 1;       // gate column 0..255
    const int kh  = tid & 1;        // reduction half

    unsigned long long wreg[16];
#pragma unroll
    for (int p = 0; p < 16; p++) {
        const int k0 = kh * 32 + 2 * p;
        wreg[p] = pk2(U[k0 * 256 + col], U[(k0 + 1) * 256 + col]);
    }

    const int cu = tid & 63;        // stage C: hidden unit
    const int cr = tid >> 6;        // stage C: task
    const int pr = tid >> 6;        // zx prefetch: task row
    const int pq = tid & 63;        // zx prefetch: float4 group

    // ---- prologue ----
    if (tid < RTASK) {
        const long long base = (long long)(b0 + tid) * TSEQ;
        const int t0 = dir ? (TSEQ - 1) : 0;
        const int t1 = dir ? (TSEQ - 2) : 1;
        idxs[0][tid] = is64 ? (int)x64[base + t0] : x32[base + t0];
        idxs[1][tid] = is64 ? (int)x64[base + t1] : x32[base + t1];
    }
    hs[cr][cu] = 0.f;
    __syncthreads();
    {   // zx for step 0
        const int tok = idxs[0][pr];
        const float4 v = *(const float4*)(zwd + (long long)tok * 256 + 4 * pq);
        *(float4*)&zxs[0][pr][4 * pq] = v;
    }
    float hreg = 0.f, creg = 0.f;
    __syncthreads();

    for (int t = 0; t < TSEQ; t++) {
        const int pcur = t & 1, pnxt = pcur ^ 1;

        const int m = idxs[pcur][cr];   // mask token (consumed in stage C)

        // prefetch zx row for step t+1
        float4 zv = make_float4(0.f, 0.f, 0.f, 0.f);
        const int have_e = (t + 1 < TSEQ);
        if (have_e) {
            const int tok = idxs[pnxt][pr];
            zv = *(const float4*)(zwd + (long long)tok * 256 + 4 * pq);
        }
        // prefetch token id for step t+2
        long long nidx = 0;
        const int have_i = (tid < RTASK) && (t + 2 < TSEQ);
        if (have_i) {
            const int tn = dir ? (TSEQ - 1 - (t + 2)) : (t + 2);
            const long long base = (long long)(b0 + tid) * TSEQ;
            nidx = is64 ? x64[base + tn] : (long long)x32[base + tn];
        }

        // ========== stage B: z = zx + h @ U ==========
#pragma unroll 2
        for (int r = 0; r < RTASK; r++) {
            const ulonglong2* hrow = (const ulonglong2*)(&hs[r][kh * 32]);
            unsigned long long a0 = 0ull, a1 = 0ull;
#pragma unroll
            for (int q = 0; q < 4; q++) {
                const ulonglong2 v0 = hrow[2 * q];
                const ulonglong2 v1 = hrow[2 * q + 1];
                ffma2(a0, v0.x, wreg[4 * q + 0]);
                ffma2(a1, v0.y, wreg[4 * q + 1]);
                ffma2(a0, v1.x, wreg[4 * q + 2]);
                ffma2(a1, v1.y, wreg[4 * q + 3]);
            }
            float p0, p1, q0, q1;
            upk2(a0, p0, p1);
            upk2(a1, q0, q1);
            float sum = (p0 + q0) + (p1 + q1);
            sum += __shfl_xor_sync(0xffffffffu, sum, 1);
            if (kh == 0) zs[r][col] = sum + zxs[pcur][r][col];
        }
        // commit zx prefetch into the other buffer (read at t+1, after 2 bars)
        if (have_e) *(float4*)&zxs[pnxt][pr][4 * pq] = zv;
        __syncthreads();

        // ========== stage C: gates + state update ==========
        {
            const float zi = zs[cr][cu];
            const float zf = zs[cr][64 + cu];
            const float zg = zs[cr][128 + cu];
            const float zo = zs[cr][192 + cu];
            const float ig = sigm(zi);
            const float fg = sigm(zf);
            const float gg = tanh_acc(zg);
            const float og = sigm(zo);
            const float cn = fg * creg + ig * gg;
            const float hn = og * tanh_acc(cn);
            if (m != 0) { creg = cn; hreg = hn; }
            hs[cr][cu] = hreg;
        }
        if (have_i) idxs[pcur][tid] = (int)nidx;   // becomes idx[t+2]
        __syncthreads();
    }

    g_h[(dir * NB + (b0 + cr)) * 64 + cu] = hreg;
}

// ============================================================================
// Head: out[b] = relu(concat(hf,hb) @ W1 + b1) @ W2 + b2
// ============================================================================
extern "C" __global__ void head_kernel(const float* __restrict__ W1,
                                       const float* __restrict__ b1,
                                       const float* __restrict__ W2,
                                       const float* __restrict__ b2,
                                       float* __restrict__ out)
{
    const int b = blockIdx.x;
    const int u = threadIdx.x;
    const float* hf = &g_h[b * 64];
    const float* hb = &g_h[(NB + b) * 64];
    float acc = b1[u];
#pragma unroll
    for (int k = 0; k < 64; k++) acc = fmaf(hf[k], W1[k * 32 + u], acc);
#pragma unroll
    for (int k = 0; k < 64; k++) acc = fmaf(hb[k], W1[(64 + k) * 32 + u], acc);
    float v = fmaxf(acc, 0.f) * W2[u];
#pragma unroll
    for (int off = 16; off > 0; off >>= 1)
        v += __shfl_xor_sync(0xffffffffu, v, off);
    if (u == 0) out[b] = v + b2[0];
}

extern "C" void kernel_launch(void* const* d_in, const int* in_sizes, int n_in,
                              void* d_out, int out_size)
{
    const void*  x   = d_in[0];
    const float* emb = (const float*)d_in[1];
    const float* Wf  = (const float*)d_in[2];
    const float* Uf  = (const float*)d_in[3];
    const float* bf  = (const float*)d_in[4];
    const float* Wb  = (const float*)d_in[5];
    const float* Ub  = (const float*)d_in[6];
    const float* bb  = (const float*)d_in[7];
    const float* W1  = (const float*)d_in[8];
    const float* b1  = (const float*)d_in[9];
    const float* W2  = (const float*)d_in[10];
    const float* b2  = (const float*)d_in[11];

    zw_kernel<<<dim3((VOCABP1 + 63) / 64, 2), 256>>>(emb, Wf, bf, Wb, bb);
    lstm_kernel<<<NBLK, 512>>>(x, Uf, Ub);
    head_kernel<<<NB, 32>>>(W1, b1, W2, b2, (float*)d_out);
}

// round 3
// speedup vs baseline: 1.8572x; 1.7464x over previous
#include <cuda_runtime.h>

#define TSEQ    1024
#define NB      512
#define RMAX    7            // max sequences per block
#define NDIRBLK 74           // blocks per direction
#define NBLK    (2 * NDIRBLK)
#define VOCABP1 50001

// Precomputed zx table: zw[dir][token][gate] = emb[token] @ W_dir + b_dir  (~102.4 MB)
__device__ float g_zw[2][VOCABP1][256];
// final hidden states: [dir][batch][64]
__device__ float g_h[2 * NB * 64];

static __device__ __forceinline__ unsigned long long pk2(float lo, float hi) {
    unsigned long long r;
    asm("mov.b64 %0, {%1,%2};" : "=l"(r) : "f"(lo), "f"(hi));
    return r;
}
static __device__ __forceinline__ void upk2(unsigned long long v, float &lo, float &hi) {
    asm("mov.b64 {%0,%1}, %2;" : "=f"(lo), "=f"(hi) : "l"(v));
}
static __device__ __forceinline__ void ffma2(unsigned long long &d,
                                             unsigned long long a,
                                             unsigned long long b) {
    asm("fma.rn.f32x2 %0, %1, %2, %0;" : "+l"(d) : "l"(a), "l"(b));
}
static __device__ __forceinline__ float sigm(float x) {
    return 1.0f / (1.0f + __expf(-x));
}
static __device__ __forceinline__ float tanh_acc(float x) {
    float e = __expf(2.0f * x);
    return 1.0f - 2.0f / (e + 1.0f);
}

// ============================================================================
// Phase 1: zw[dir][v][j] = sum_k emb[v][k] * W_dir[k][j] + b_dir[j]
// ============================================================================
extern "C" __global__ void __launch_bounds__(256)
zw_kernel(const float* __restrict__ emb,
          const float* __restrict__ Wf, const float* __restrict__ bf,
          const float* __restrict__ Wb, const float* __restrict__ bb)
{
    __shared__ __align__(16) float ebuf[64][64];
    const int dir  = blockIdx.y;
    const int base = blockIdx.x * 64;
    const int j    = threadIdx.x;
    const float* W  = dir ? Wb : Wf;
    const float* bv = dir ? bb : bf;

    unsigned long long wreg[32];
#pragma unroll
    for (int p = 0; p < 32; p++)
        wreg[p] = pk2(W[(2 * p) * 256 + j], W[(2 * p + 1) * 256 + j]);
    const float bj = bv[j];

#pragma unroll
    for (int i = 0; i < 16; i++) {
        const int lin = i * 256 + j;
        const int r = lin >> 6, c = lin & 63;
        const int row = base + r;
        ebuf[r][c] = (row < VOCABP1) ? emb[(long long)row * 64 + c] : 0.f;
    }
    __syncthreads();

    float* outp = &g_zw[dir][0][0];
#pragma unroll 1
    for (int r = 0; r < 64; r++) {
        if (base + r >= VOCABP1) break;
        const ulonglong2* srow = (const ulonglong2*)(&ebuf[r][0]);
        unsigned long long a0 = 0ull, a1 = 0ull;
#pragma unroll
        for (int q = 0; q < 8; q++) {
            const ulonglong2 v0 = srow[2 * q];
            const ulonglong2 v1 = srow[2 * q + 1];
            ffma2(a0, v0.x, wreg[4 * q + 0]);
            ffma2(a1, v0.y, wreg[4 * q + 1]);
            ffma2(a0, v1.x, wreg[4 * q + 2]);
            ffma2(a1, v1.y, wreg[4 * q + 3]);
        }
        float p0, p1, q0, q1;
        upk2(a0, p0, p1);
        upk2(a1, q0, q1);
        outp[(long long)(base + r) * 256 + j] = bj + ((p0 + q0) + (p1 + q1));
    }
}

// ============================================================================
// Phase 2: recurrent h@U + gates.
// 148 blocks x 512 threads (16 warps). 74 blocks/direction, <=7 sequences each.
// Thread layout (stage B): col = tid&255 (gate column), rhalf = tid>>8.
//   rhalf=0 handles rows 0..3, rhalf=1 handles rows 4..6 (SMSP-balanced).
//   Full k=64 in 32 packed f32x2 registers; all hs reads are warp-broadcast.
// ============================================================================
extern "C" __global__ void __launch_bounds__(512, 1)
lstm_kernel(const void* __restrict__ xraw,
            const float* __restrict__ Uf, const float* __restrict__ Ub)
{
    __shared__ __align__(16) float hs[RMAX][64];          // hidden state
    __shared__ __align__(16) float zs[RMAX][256];         // gate pre-activations
    __shared__ __align__(16) float zxs[2][RMAX][256];     // zx double buffer
    __shared__ int   idxs[2][8];                          // token ids, ping-pong

    const int tid = threadIdx.x;
    const int dir   = (blockIdx.x >= NDIRBLK) ? 1 : 0;
    const int bslot = blockIdx.x - dir * NDIRBLK;
    const int base  = bslot * RMAX;
    const int nrows = min(RMAX, NB - base);

    const int*       x32 = (const int*)xraw;
    const long long* x64 = (const long long*)xraw;
    const bool is64 = ((x32[1] | x32[3] | x32[5] | x32[7]) == 0);

    const float* U   = dir ? Ub : Uf;
    const float* zwd = &g_zw[dir][0][0];

    const int col   = tid & 255;
    const int rhalf = tid >> 8;
    const int r0    = rhalf ? 4 : 0;
    const int rcnt  = rhalf ? 3 : 4;

    unsigned long long wreg[32];
#pragma unroll
    for (int p = 0; p < 32; p++)
        wreg[p] = pk2(U[(2 * p) * 256 + col], U[(2 * p + 1) * 256 + col]);

    const int cu = tid & 63;        // stage C: hidden unit
    const int cr = tid >> 6;        // stage C: task (0..7)
    const int pr = tid >> 6;        // zx prefetch: task row
    const int pq = tid & 63;        // zx prefetch: float4 group

    // ---- prologue ----
    if (tid < nrows) {
        const long long xb = (long long)(base + tid) * TSEQ;
        const int t0 = dir ? (TSEQ - 1) : 0;
        const int t1 = dir ? (TSEQ - 2) : 1;
        idxs[0][tid] = is64 ? (int)x64[xb + t0] : x32[xb + t0];
        idxs[1][tid] = is64 ? (int)x64[xb + t1] : x32[xb + t1];
    }
    if (cr < RMAX) hs[cr][cu] = 0.f;
    __syncthreads();
    if (pr < nrows) {   // zx for step 0
        const int tok = idxs[0][pr];
        const float4 v = *(const float4*)(zwd + (long long)tok * 256 + 4 * pq);
        *(float4*)&zxs[0][pr][4 * pq] = v;
    }
    float hreg = 0.f, creg = 0.f;
    __syncthreads();

    for (int t = 0; t < TSEQ; t++) {
        const int pcur = t & 1, pnxt = pcur ^ 1;

        const int m = (cr < nrows) ? idxs[pcur][cr] : 0;   // mask token

        // prefetch zx row for step t+1
        float4 zv = make_float4(0.f, 0.f, 0.f, 0.f);
        const int have_e = (t + 1 < TSEQ) && (pr < nrows);
        if (have_e) {
            const int tok = idxs[pnxt][pr];
            zv = *(const float4*)(zwd + (long long)tok * 256 + 4 * pq);
        }
        // prefetch token id for step t+2
        long long nidx = 0;
        const int have_i = (tid < nrows) && (t + 2 < TSEQ);
        if (have_i) {
            const int tn = dir ? (TSEQ - 1 - (t + 2)) : (t + 2);
            const long long xb = (long long)(base + tid) * TSEQ;
            nidx = is64 ? x64[xb + tn] : (long long)x32[xb + tn];
        }

        // ========== stage B: z = zx + h @ U ==========
#pragma unroll
        for (int i = 0; i < 4; i++) {
            if (i >= rcnt) break;
            const int r = r0 + i;
            if (r >= nrows) break;
            const ulonglong2* hp = (const ulonglong2*)(&hs[r][0]);
            unsigned long long a0 = 0ull, a1 = 0ull;
#pragma unroll
            for (int q = 0; q < 8; q++) {
                const ulonglong2 v0 = hp[2 * q];
                const ulonglong2 v1 = hp[2 * q + 1];
                ffma2(a0, v0.x, wreg[4 * q + 0]);
                ffma2(a1, v0.y, wreg[4 * q + 1]);
                ffma2(a0, v1.x, wreg[4 * q + 2]);
                ffma2(a1, v1.y, wreg[4 * q + 3]);
            }
            float p0, p1, q0, q1;
            upk2(a0, p0, p1);
            upk2(a1, q0, q1);
            zs[r][col] = zxs[pcur][r][col] + ((p0 + q0) + (p1 + q1));
        }
        // commit zx prefetch into the other buffer (read at t+1 after bar)
        if (have_e) *(float4*)&zxs[pnxt][pr][4 * pq] = zv;
        __syncthreads();

        // ========== stage C: gates + state update ==========
        if (cr < nrows) {
            const float zi = zs[cr][cu];
            const float zf = zs[cr][64 + cu];
            const float zg = zs[cr][128 + cu];
            const float zo = zs[cr][192 + cu];
            const float ig = sigm(zi);
            const float fg = sigm(zf);
            const float gg = tanh_acc(zg);
            const float og = sigm(zo);
            const float cn = fg * creg + ig * gg;
            const float hn = og * tanh_acc(cn);
            if (m != 0) { creg = cn; hreg = hn; }
            hs[cr][cu] = hreg;
        }
        if (have_i) idxs[pcur][tid] = (int)nidx;   // becomes idx[t+2]
        __syncthreads();
    }

    if (cr < nrows)
        g_h[(dir * NB + (base + cr)) * 64 + cu] = hreg;
}

// ============================================================================
// Head: out[b] = relu(concat(hf,hb) @ W1 + b1) @ W2 + b2
// ============================================================================
extern "C" __global__ void head_kernel(const float* __restrict__ W1,
                                       const float* __restrict__ b1,
                                       const float* __restrict__ W2,
                                       const float* __restrict__ b2,
                                       float* __restrict__ out)
{
    const int b = blockIdx.x;
    const int u = threadIdx.x;
    const float* hf = &g_h[b * 64];
    const float* hb = &g_h[(NB + b) * 64];
    float acc = b1[u];
#pragma unroll
    for (int k = 0; k < 64; k++) acc = fmaf(hf[k], W1[k * 32 + u], acc);
#pragma unroll
    for (int k = 0; k < 64; k++) acc = fmaf(hb[k], W1[(64 + k) * 32 + u], acc);
    float v = fmaxf(acc, 0.f) * W2[u];
#pragma unroll
    for (int off = 16; off > 0; off >>= 1)
        v += __shfl_xor_sync(0xffffffffu, v, off);
    if (u == 0) out[b] = v + b2[0];
}

extern "C" void kernel_launch(void* const* d_in, const int* in_sizes, int n_in,
                              void* d_out, int out_size)
{
    const void*  x   = d_in[0];
    const float* emb = (const float*)d_in[1];
    const float* Wf  = (const float*)d_in[2];
    const float* Uf  = (const float*)d_in[3];
    const float* bf  = (const float*)d_in[4];
    const float* Wb  = (const float*)d_in[5];
    const float* Ub  = (const float*)d_in[6];
    const float* bb  = (const float*)d_in[7];
    const float* W1  = (const float*)d_in[8];
    const float* b1  = (const float*)d_in[9];
    const float* W2  = (const float*)d_in[10];
    const float* b2  = (const float*)d_in[11];

    zw_kernel<<<dim3((VOCABP1 + 63) / 64, 2), 256>>>(emb, Wf, bf, Wb, bb);
    lstm_kernel<<<NBLK, 512>>>(x, Uf, Ub);
    head_kernel<<<NB, 32>>>(W1, b1, W2, b2, (float*)d_out);
}